// round 1
// baseline (speedup 1.0000x reference)
#include <cuda_runtime.h>

#define NN 2048
#define EE 16384
#define DIN 1280
#define ROWW 64            // uint32 words per 2048-bit ego row
#define NEGBIG (-1e30f)

// -------- device scratch (no allocation allowed) --------
__device__ float    g_h[NN];            // per-node scalar feature h = x_orig @ W2^T
__device__ unsigned g_rowM[NN * ROWW];  // row-major ego bitmasks, 256B per ego
__device__ int      g_head[NN];         // incoming-edge linked list heads (by dst)
__device__ int      g_next[EE];         // linked list next pointers

// ---------------- h = x_orig @ W2^T  (one warp per row) ----------------
__global__ void k_h(const float* __restrict__ xo, const float* __restrict__ W2) {
    int warp = (blockIdx.x * blockDim.x + threadIdx.x) >> 5;
    int lane = threadIdx.x & 31;
    if (warp >= NN) return;
    const float4* xr = (const float4*)(xo + (size_t)warp * DIN);
    const float4* wr = (const float4*)W2;
    float acc = 0.f;
#pragma unroll
    for (int i = 0; i < DIN / 128; i++) {     // 1280/4 floats4 / 32 lanes = 10
        float4 a = xr[lane + i * 32];
        float4 b = wr[lane + i * 32];
        acc += a.x * b.x + a.y * b.y + a.z * b.z + a.w * b.w;
    }
#pragma unroll
    for (int off = 16; off; off >>= 1) acc += __shfl_xor_sync(0xffffffffu, acc, off);
    if (lane == 0) g_h[warp] = acc;
}

// ---------------- incoming-edge linked lists ----------------
__global__ void k_head_init() {
    int i = blockIdx.x * blockDim.x + threadIdx.x;
    if (i < NN) g_head[i] = -1;
}

__global__ void k_lists(const int* __restrict__ ei) {
    int e = blockIdx.x * blockDim.x + threadIdx.x;
    if (e < EE) {
        int d = ei[EE + e];                      // dst
        g_next[e] = atomicExch(&g_head[d], e);
    }
}

// ---------------- 2-hop masks: 32 egos per block, bit-parallel ----------------
__global__ void k_hops(const int* __restrict__ ei) {
    __shared__ unsigned mOld[NN];
    __shared__ unsigned mNew[NN];
    const int v0 = blockIdx.x * 32;
    const int* __restrict__ src = ei;
    const int* __restrict__ dst = ei + EE;

    for (int i = threadIdx.x; i < NN; i += blockDim.x) mOld[i] = 0u;
    __syncthreads();
    if (threadIdx.x < 32) mOld[v0 + threadIdx.x] = 1u << threadIdx.x;
    __syncthreads();

    for (int hop = 0; hop < 2; hop++) {
        for (int i = threadIdx.x; i < NN; i += blockDim.x) mNew[i] = mOld[i];
        __syncthreads();
        for (int e = threadIdx.x; e < EE; e += blockDim.x) {
            unsigned val = mOld[dst[e]];
            if (val) atomicOr(&mNew[src[e]], val);
        }
        __syncthreads();
        for (int i = threadIdx.x; i < NN; i += blockDim.x) mOld[i] = mNew[i];
        __syncthreads();
    }

    // transpose column bits -> row-major 2048-bit ego rows via ballot
    int warp = threadIdx.x >> 5, lane = threadIdx.x & 31;
    int nw = blockDim.x >> 5;
    for (int w = warp; w < ROWW; w += nw) {
        unsigned m = mOld[w * 32 + lane];
#pragma unroll
        for (int k = 0; k < 32; k++) {
            unsigned b = __ballot_sync(0xffffffffu, (m >> k) & 1u);
            if (lane == k) g_rowM[(size_t)(v0 + k) * ROWW + w] = b;
        }
    }
}

// ---------------- per-ego GAT + segment softmax + ego softmax ----------------
__global__ void k_ego(const int* __restrict__ ei,
                      const float* __restrict__ att_src,
                      const float* __restrict__ att_dst,
                      const float* __restrict__ bias,
                      float* __restrict__ out, int write_mask) {
    __shared__ unsigned row[ROWW];
    __shared__ float gat[NN];
    __shared__ float red[33];
    const int v = blockIdx.x;
    const int* __restrict__ srcA = ei;
    const float as = att_src[0], ad = att_dst[0], bi = bias[0];

    if (threadIdx.x < ROWW) row[threadIdx.x] = g_rowM[(size_t)v * ROWW + threadIdx.x];
    __syncthreads();

    for (int i = threadIdx.x; i < NN; i += blockDim.x) {
        if ((row[i >> 5] >> (i & 31)) & 1u) {
            float hi  = g_h[i];
            float adh = ad * hi;
            float z   = as * hi + adh;
            float self = z > 0.f ? z : 0.2f * z;
            float m = self;
            for (int e = g_head[i]; e >= 0; e = g_next[e]) {
                int s = srcA[e];
                if ((row[s >> 5] >> (s & 31)) & 1u) {
                    float zz = as * g_h[s] + adh;
                    float lg = zz > 0.f ? zz : 0.2f * zz;
                    m = fmaxf(m, lg);
                }
            }
            float w = __expf(self - m);
            float denom = w, num = w * hi;
            for (int e = g_head[i]; e >= 0; e = g_next[e]) {
                int s = srcA[e];
                if ((row[s >> 5] >> (s & 31)) & 1u) {
                    float hs = g_h[s];
                    float zz = as * hs + adh;
                    float lg = zz > 0.f ? zz : 0.2f * zz;
                    float ww = __expf(lg - m);
                    denom += ww;
                    num   += ww * hs;
                }
            }
            gat[i] = num / denom + bi;
        } else {
            gat[i] = NEGBIG;
        }
    }
    __syncthreads();

    int lane = threadIdx.x & 31, wp = threadIdx.x >> 5;
    int nw = blockDim.x >> 5;

    // block-reduce max over ego nodes
    float mx = NEGBIG;
    for (int i = threadIdx.x; i < NN; i += blockDim.x) mx = fmaxf(mx, gat[i]);
#pragma unroll
    for (int off = 16; off; off >>= 1) mx = fmaxf(mx, __shfl_xor_sync(0xffffffffu, mx, off));
    if (lane == 0) red[wp] = mx;
    __syncthreads();
    if (threadIdx.x < 32) {
        float t = (threadIdx.x < nw) ? red[threadIdx.x] : NEGBIG;
#pragma unroll
        for (int off = 16; off; off >>= 1) t = fmaxf(t, __shfl_xor_sync(0xffffffffu, t, off));
        if (threadIdx.x == 0) red[32] = t;
    }
    __syncthreads();
    mx = red[32];
    __syncthreads();

    // exp and block-reduce sum
    float sm = 0.f;
    for (int i = threadIdx.x; i < NN; i += blockDim.x) {
        unsigned bit = (row[i >> 5] >> (i & 31)) & 1u;
        float e = bit ? __expf(gat[i] - mx) : 0.f;
        gat[i] = e;
        sm += e;
    }
#pragma unroll
    for (int off = 16; off; off >>= 1) sm += __shfl_xor_sync(0xffffffffu, sm, off);
    if (lane == 0) red[wp] = sm;
    __syncthreads();
    if (threadIdx.x < 32) {
        float t = (threadIdx.x < nw) ? red[threadIdx.x] : 0.f;
#pragma unroll
        for (int off = 16; off; off >>= 1) t += __shfl_xor_sync(0xffffffffu, t, off);
        if (threadIdx.x == 0) red[32] = t;
    }
    __syncthreads();
    float inv = 1.f / red[32];

    float* so = out + (size_t)v * NN;
    float* mo = out + (size_t)NN * NN + (size_t)v * NN;
    for (int i = threadIdx.x; i < NN; i += blockDim.x) {
        unsigned bit = (row[i >> 5] >> (i & 31)) & 1u;
        so[i] = bit ? gat[i] * inv : 0.f;
        if (write_mask) mo[i] = bit ? 1.f : 0.f;
    }
}

// ---------------- launch ----------------
extern "C" void kernel_launch(void* const* d_in, const int* in_sizes, int n_in,
                              void* d_out, int out_size) {
    // inputs: 0:x 1:x_orig 2:edge_index 3:batch 4:W2 5:att_src 6:att_dst 7:bias
    const float* x_orig  = (const float*)d_in[1];
    const int*   ei      = (const int*)d_in[2];
    const float* W2      = (const float*)d_in[4];
    const float* att_src = (const float*)d_in[5];
    const float* att_dst = (const float*)d_in[6];
    const float* bias    = (const float*)d_in[7];
    float* out = (float*)d_out;
    int write_mask = (out_size >= 2 * NN * NN) ? 1 : 0;

    k_h<<<NN / 8, 256>>>(x_orig, W2);         // 2048 warps, one per row
    k_head_init<<<NN / 256, 256>>>();
    k_lists<<<EE / 256, 256>>>(ei);
    k_hops<<<NN / 32, 256>>>(ei);
    k_ego<<<NN, 256>>>(ei, att_src, att_dst, bias, out, write_mask);
}

// round 2
// speedup vs baseline: 4.4651x; 4.4651x over previous
#include <cuda_runtime.h>

#define NN 2048
#define EE 16384
#define DIN 1280
#define ROWW 64            // uint32 words per 2048-bit ego row
#define MAXDEG 64          // fixed-stride CSR slot capacity (P(in-deg>64) ~ 1e-30)
#define NEGBIG (-1e30f)

// -------- device scratch (no allocation allowed) --------
__device__ float    g_h[NN];                 // h = x_orig @ W2^T
__device__ unsigned g_rowM[NN * ROWW];       // row-major ego bitmasks (256B/ego)
__device__ int      g_deg[NN];               // in-degree counters
__device__ int      g_nsrc[NN * MAXDEG];     // in-edge source ids, per dst
__device__ float    g_nh[NN * MAXDEG];       // h[src] payload, per dst

// ---------------- h = x_orig @ W2^T (one warp per row) + zero scratch ----------------
__global__ void k_h(const float* __restrict__ xo, const float* __restrict__ W2) {
    int warp = (blockIdx.x * blockDim.x + threadIdx.x) >> 5;
    int lane = threadIdx.x & 31;
    const float4* xr = (const float4*)(xo + (size_t)warp * DIN);
    const float4* wr = (const float4*)W2;
    float acc = 0.f;
#pragma unroll
    for (int i = 0; i < DIN / 128; i++) {     // 10 float4 per lane
        float4 a = xr[lane + i * 32];
        float4 b = wr[lane + i * 32];
        acc += a.x * b.x + a.y * b.y + a.z * b.z + a.w * b.w;
    }
#pragma unroll
    for (int off = 16; off; off >>= 1) acc += __shfl_xor_sync(0xffffffffu, acc, off);
    if (lane == 0) {
        g_h[warp] = acc;
        g_deg[warp] = 0;
    }
    // zero this ego's bitmask row (used by k_hops next launch)
    g_rowM[(size_t)warp * ROWW + lane]      = 0u;
    g_rowM[(size_t)warp * ROWW + 32 + lane] = 0u;
}

// ---------------- fixed-stride in-edge CSR scatter ----------------
__global__ void k_scatter(const int* __restrict__ ei) {
    int e = blockIdx.x * blockDim.x + threadIdx.x;
    if (e < EE) {
        int s = ei[e];
        int d = ei[EE + e];
        int p = atomicAdd(&g_deg[d], 1);
        if (p < MAXDEG) {
            g_nsrc[d * MAXDEG + p] = s;
            g_nh[d * MAXDEG + p]   = g_h[s];
        }
    }
}

// ---------------- sparse 2-hop masks: one warp per ego ----------------
__global__ void k_hops() {
    int warp = (blockIdx.x * blockDim.x + threadIdx.x) >> 5;
    int lane = threadIdx.x & 31;
    int v = warp;
    unsigned* row = g_rowM + (size_t)v * ROWW;
    if (lane == 0) atomicOr(&row[v >> 5], 1u << (v & 31));
    int dv = min(g_deg[v], MAXDEG);
    for (int k = lane; k < dv; k += 32) {
        int s = g_nsrc[v * MAXDEG + k];
        atomicOr(&row[s >> 5], 1u << (s & 31));
        int ds = min(g_deg[s], MAXDEG);
        for (int j = 0; j < ds; j++) {
            int t = g_nsrc[s * MAXDEG + j];
            atomicOr(&row[t >> 5], 1u << (t & 31));
        }
    }
}

// ---------------- per-ego GAT + segment softmax + ego softmax ----------------
__global__ void __launch_bounds__(256) k_ego(const float* __restrict__ att_src,
                      const float* __restrict__ att_dst,
                      const float* __restrict__ bias,
                      float* __restrict__ out, int write_mask) {
    __shared__ unsigned row[ROWW];
    __shared__ int   list[NN];
    __shared__ float vals[NN];
    __shared__ float red[33];
    __shared__ int   cnt;
    const int v = blockIdx.x;
    const float as = att_src[0], ad = att_dst[0], bi = bias[0];
    const int tid = threadIdx.x, lane = tid & 31, wp = tid >> 5;

    if (tid == 0) cnt = 0;
    if (tid < ROWW) row[tid] = g_rowM[(size_t)v * ROWW + tid];
    __syncthreads();

    // compact list of ego-node ids
    if (tid < ROWW) {
        unsigned m = row[tid];
        while (m) {
            int b = __ffs(m) - 1;
            m &= m - 1;
            int p = atomicAdd(&cnt, 1);
            list[p] = tid * 32 + b;
        }
    }
    __syncthreads();
    const int n = cnt;

    // pass 1: per-node GAT (single-pass online segment softmax), track block max
    float mx = NEGBIG;
    for (int idx = tid; idx < n; idx += 256) {
        int i = list[idx];
        float hi  = g_h[i];
        float adh = ad * hi;
        float z   = as * hi + adh;
        float m   = z > 0.f ? z : 0.2f * z;   // self-loop logit
        float denom = 1.f, num = hi;          // relative to m
        int base = i * MAXDEG;
        int dv = min(g_deg[i], MAXDEG);
#pragma unroll 4
        for (int j = 0; j < dv; j++) {
            int s = g_nsrc[base + j];
            if ((row[s >> 5] >> (s & 31)) & 1u) {
                float hs = g_nh[base + j];
                float zz = as * hs + adh;
                float lg = zz > 0.f ? zz : 0.2f * zz;
                if (lg > m) {
                    float sc = __expf(m - lg);
                    denom *= sc; num *= sc; m = lg;
                }
                float w = __expf(lg - m);
                denom += w; num += w * hs;
            }
        }
        float gat = num / denom + bi;
        vals[i] = gat;
        mx = fmaxf(mx, gat);
    }
    // block-reduce max
#pragma unroll
    for (int off = 16; off; off >>= 1) mx = fmaxf(mx, __shfl_xor_sync(0xffffffffu, mx, off));
    if (lane == 0) red[wp] = mx;
    __syncthreads();
    if (tid < 32) {
        float t = (tid < 8) ? red[tid] : NEGBIG;
#pragma unroll
        for (int off = 4; off; off >>= 1) t = fmaxf(t, __shfl_xor_sync(0xffffffffu, t, off));
        if (tid == 0) red[32] = t;
    }
    __syncthreads();
    mx = red[32];
    __syncthreads();

    // pass 2: exp + block-reduce sum
    float sm = 0.f;
    for (int idx = tid; idx < n; idx += 256) {
        int i = list[idx];
        float e = __expf(vals[i] - mx);
        vals[i] = e;
        sm += e;
    }
#pragma unroll
    for (int off = 16; off; off >>= 1) sm += __shfl_xor_sync(0xffffffffu, sm, off);
    if (lane == 0) red[wp] = sm;
    __syncthreads();
    if (tid < 32) {
        float t = (tid < 8) ? red[tid] : 0.f;
#pragma unroll
        for (int off = 4; off; off >>= 1) t += __shfl_xor_sync(0xffffffffu, t, off);
        if (tid == 0) red[32] = t;
    }
    __syncthreads();
    const float inv = 1.f / red[32];

    // pass 3: vectorized row writes (scores + mask)
    float4* so4 = (float4*)(out + (size_t)v * NN);
    float4* mo4 = (float4*)(out + (size_t)NN * NN + (size_t)v * NN);
    for (int t = tid; t < NN / 4; t += 256) {
        int i0 = t * 4;
        unsigned w = row[i0 >> 5] >> (i0 & 31);   // 4 bits at i0..i0+3
        float4 a, b;
        a.x = (w & 1u) ? vals[i0 + 0] * inv : 0.f;  b.x = (w & 1u) ? 1.f : 0.f;
        a.y = (w & 2u) ? vals[i0 + 1] * inv : 0.f;  b.y = (w & 2u) ? 1.f : 0.f;
        a.z = (w & 4u) ? vals[i0 + 2] * inv : 0.f;  b.z = (w & 4u) ? 1.f : 0.f;
        a.w = (w & 8u) ? vals[i0 + 3] * inv : 0.f;  b.w = (w & 8u) ? 1.f : 0.f;
        so4[t] = a;
        if (write_mask) mo4[t] = b;
    }
}

// ---------------- launch ----------------
extern "C" void kernel_launch(void* const* d_in, const int* in_sizes, int n_in,
                              void* d_out, int out_size) {
    // inputs: 0:x 1:x_orig 2:edge_index 3:batch 4:W2 5:att_src 6:att_dst 7:bias
    const float* x_orig  = (const float*)d_in[1];
    const int*   ei      = (const int*)d_in[2];
    const float* W2      = (const float*)d_in[4];
    const float* att_src = (const float*)d_in[5];
    const float* att_dst = (const float*)d_in[6];
    const float* bias    = (const float*)d_in[7];
    float* out = (float*)d_out;
    int write_mask = (out_size >= 2 * NN * NN) ? 1 : 0;

    k_h<<<NN / 8, 256>>>(x_orig, W2);       // 2048 warps: h, zero deg + rowM
    k_scatter<<<EE / 256, 256>>>(ei);       // fixed-stride in-edge CSR
    k_hops<<<NN / 8, 256>>>();              // one warp per ego, sparse expansion
    k_ego<<<NN, 256>>>(att_src, att_dst, bias, out, write_mask);
}